// round 12
// baseline (speedup 1.0000x reference)
#include <cuda_runtime.h>
#include <cuda_bf16.h>
#include <cstdint>
#include <math.h>

#define DIM    256
#define HEADS  8
#define HD     32
#define N1V    256
#define N2V    256
#define BTOT   256
#define NWIN   128
#define TBL    1575
#define MTOT   (BTOT * N1V)

typedef unsigned long long ull;

// ---------------- scratch (device globals; no allocation) ----------------
__device__ float d_qh [MTOT * DIM];              // scaled Q proj
__device__ float d_kvh[MTOT * 2 * DIM];          // K|V proj
__device__ float d_x  [MTOT * DIM];              // attention output
__device__ float d_biasF[HEADS * N1V * N2V];     // expanded rel-pos bias (2MB)

// ---------------- packed f32x2 helpers ----------------
__device__ __forceinline__ ull pack2(float x, float y) {
    ull r; asm("mov.b64 %0, {%1, %2};" : "=l"(r) : "f"(x), "f"(y)); return r;
}
__device__ __forceinline__ void unpack2(ull v, float& x, float& y) {
    asm("mov.b64 {%0, %1}, %2;" : "=f"(x), "=f"(y) : "l"(v));
}
__device__ __forceinline__ void ffma2(ull& d, ull a, ull b) {
    asm("fma.rn.f32x2 %0, %1, %2, %0;" : "+l"(d) : "l"(a), "l"(b));
}

// ---------------- FFMA2 NT SGEMM, double-buffered smem ---------------------
__global__ void __launch_bounds__(256) gemm_nt(
    const float* __restrict__ A, const float* __restrict__ B,
    const float* __restrict__ bias, float* __restrict__ C,
    int M, int N, int K, float alpha)
{
    __shared__ float As[2][16][132];
    __shared__ float Bs[2][16][132];
    const int m0  = blockIdx.y * 128;
    const int n0  = blockIdx.x * 128;
    const int tid = threadIdx.x;
    const int tr  = tid >> 4;
    const int tc  = tid & 15;

    int lr[2], lc[2];
#pragma unroll
    for (int i = 0; i < 2; i++) {
        int li = tid + i * 256;
        lr[i] = li >> 2;
        lc[i] = (li & 3) << 2;
    }

    ull acc2[8][4];
#pragma unroll
    for (int i = 0; i < 8; i++)
#pragma unroll
        for (int j = 0; j < 4; j++) acc2[i][j] = 0ull;

    const int NT = K >> 4;

#pragma unroll
    for (int i = 0; i < 2; i++) {
        float4 va = *(const float4*)(A + (size_t)(m0 + lr[i]) * K + lc[i]);
        As[0][lc[i] + 0][lr[i]] = va.x; As[0][lc[i] + 1][lr[i]] = va.y;
        As[0][lc[i] + 2][lr[i]] = va.z; As[0][lc[i] + 3][lr[i]] = va.w;
        float4 vb = *(const float4*)(B + (size_t)(n0 + lr[i]) * K + lc[i]);
        Bs[0][lc[i] + 0][lr[i]] = vb.x; Bs[0][lc[i] + 1][lr[i]] = vb.y;
        Bs[0][lc[i] + 2][lr[i]] = vb.z; Bs[0][lc[i] + 3][lr[i]] = vb.w;
    }
    __syncthreads();

#pragma unroll 1
    for (int kt = 0; kt < NT; kt++) {
        const int cur = kt & 1;
        float4 na[2], nb[2];
        const bool more = (kt + 1 < NT);
        if (more) {
            const int k0 = (kt + 1) << 4;
#pragma unroll
            for (int i = 0; i < 2; i++) {
                na[i] = *(const float4*)(A + (size_t)(m0 + lr[i]) * K + k0 + lc[i]);
                nb[i] = *(const float4*)(B + (size_t)(n0 + lr[i]) * K + k0 + lc[i]);
            }
        }
#pragma unroll
        for (int kk = 0; kk < 16; kk++) {
            float4 a0 = *(const float4*)&As[cur][kk][tr * 8];
            float4 a1 = *(const float4*)&As[cur][kk][tr * 8 + 4];
            ull b2[4];
#pragma unroll
            for (int j = 0; j < 4; j++)
                b2[j] = *(const ull*)&Bs[cur][kk][tc * 8 + 2 * j];
            ull ad[8];
            ad[0] = pack2(a0.x, a0.x); ad[1] = pack2(a0.y, a0.y);
            ad[2] = pack2(a0.z, a0.z); ad[3] = pack2(a0.w, a0.w);
            ad[4] = pack2(a1.x, a1.x); ad[5] = pack2(a1.y, a1.y);
            ad[6] = pack2(a1.z, a1.z); ad[7] = pack2(a1.w, a1.w);
#pragma unroll
            for (int i = 0; i < 8; i++)
#pragma unroll
                for (int j = 0; j < 4; j++)
                    ffma2(acc2[i][j], ad[i], b2[j]);
        }
        if (more) {
            const int nxt = cur ^ 1;
#pragma unroll
            for (int i = 0; i < 2; i++) {
                As[nxt][lc[i] + 0][lr[i]] = na[i].x; As[nxt][lc[i] + 1][lr[i]] = na[i].y;
                As[nxt][lc[i] + 2][lr[i]] = na[i].z; As[nxt][lc[i] + 3][lr[i]] = na[i].w;
                Bs[nxt][lc[i] + 0][lr[i]] = nb[i].x; Bs[nxt][lc[i] + 1][lr[i]] = nb[i].y;
                Bs[nxt][lc[i] + 2][lr[i]] = nb[i].z; Bs[nxt][lc[i] + 3][lr[i]] = nb[i].w;
            }
            __syncthreads();
        }
    }

#pragma unroll
    for (int i = 0; i < 8; i++) {
        int r = m0 + tr * 8 + i;
#pragma unroll
        for (int j = 0; j < 4; j++) {
            int c = n0 + tc * 8 + 2 * j;
            float x, y;
            unpack2(acc2[i][j], x, y);
            float2 v;
            v.x = alpha * (x + bias[c]);
            v.y = alpha * (y + bias[c + 1]);
            *(float2*)(C + (size_t)r * N + c) = v;
        }
    }
}

// ---------------- rel-pos bias expansion: biasF[h][q][k] -------------------
__global__ void __launch_bounds__(256) bias_pre(
    const float* __restrict__ btab_g, const int* __restrict__ rel,
    float* __restrict__ biasF)
{
    int idx = blockIdx.x * 256 + threadIdx.x;
    int ri  = rel[idx] * HEADS;
#pragma unroll
    for (int h = 0; h < HEADS; h++)
        biasF[h * (N1V * N2V) + idx] = btab_g[ri + h];
}

// ---------------- attention v5: lane-pair ffma2, 2 blocks/SM ---------------
// QK: thread (qg=tid>>4, kg=tid&15) -> 4 queries x 16 keys, two 8-key batches,
//     lanes of each f32x2 accumulate even/odd channels (zero-pack reinterpret).
// PV: thread (q2=tid>>3, dg=tid&7) -> 2 queries x 4 dims, p duplicated per use.
#define SK 36
#define SQ 36
#define SP 260
#define KV_OFF 0
#define PB_OFF (256 * SK)                        // 9216 floats
#define ATTN_SMEM_FLOATS (PB_OFF + 64 * SP)      // 25856 floats
#define ATTN_SMEM_BYTES (ATTN_SMEM_FLOATS * 4)   // 103424 B -> 2 blocks/SM

__global__ void __launch_bounds__(256, 2) attn_kernel(
    const float* __restrict__ qh, const float* __restrict__ kvh,
    const float* __restrict__ mask, const float* __restrict__ biasF,
    float* __restrict__ xout)
{
    extern __shared__ float smem[];
    float* Ks = smem + KV_OFF;     // K tile, later V tile
    float* Pb = smem + PB_OFF;     // Qs alias, then mask+bias stage, then P
    float* Qs = Pb;

    const int tid = threadIdx.x;
    const int qg  = tid >> 4;
    const int kg  = tid & 15;
    const int q0  = blockIdx.x * 64;
    const int h   = blockIdx.y;
    const int b   = blockIdx.z;
    const int w   = b & (NWIN - 1);
    const int qi0 = qg * 4;

    // ---- load Q (64x32, into Pb head) and K (256x32) ----
    {
        const float* qbase = qh + ((size_t)(b * N1V + q0)) * DIM + h * HD;
#pragma unroll
        for (int i = 0; i < 2; i++) {
            int li = tid + i * 256;
            int r  = li >> 3;
            int c4 = (li & 7) * 4;
            *(float4*)&Qs[r * SQ + c4] =
                *(const float4*)(qbase + (size_t)r * DIM + c4);
        }
        const float* kbase = kvh + ((size_t)b * N2V) * (2 * DIM) + h * HD;
#pragma unroll
        for (int i = 0; i < 8; i++) {
            int li = tid + i * 256;
            int r  = li >> 3;
            int c4 = (li & 7) * 4;
            *(float4*)&Ks[r * SK + c4] =
                *(const float4*)(kbase + (size_t)r * (2 * DIM) + c4);
        }
    }
    __syncthreads();

    // ---- QK: lane-pair ffma2, two 8-key batches (acc regs bounded) ----
    float s[4][16];
#pragma unroll 1
    for (int half = 0; half < 2; half++) {
        ull acc2[4][8];
#pragma unroll
        for (int i = 0; i < 4; i++)
#pragma unroll
            for (int j = 0; j < 8; j++) acc2[i][j] = 0ull;

#pragma unroll 2
        for (int c4 = 0; c4 < 8; c4++) {
            ulonglong2 q2[4];
#pragma unroll
            for (int i = 0; i < 4; i++)
                q2[i] = *(const ulonglong2*)&Qs[(qi0 + i) * SQ + c4 * 4];
#pragma unroll
            for (int jj = 0; jj < 8; jj++) {
                const int j = half * 8 + jj;
                ulonglong2 kv = *(const ulonglong2*)&Ks[(16 * j + kg) * SK + c4 * 4];
#pragma unroll
                for (int i = 0; i < 4; i++) {
                    ffma2(acc2[i][jj], q2[i].x, kv.x);
                    ffma2(acc2[i][jj], q2[i].y, kv.y);
                }
            }
        }
#pragma unroll
        for (int i = 0; i < 4; i++)
#pragma unroll
            for (int jj = 0; jj < 8; jj++) {
                float x, y;
                unpack2(acc2[i][jj], x, y);
                s[i][half * 8 + jj] = x + y;
            }
    }
    __syncthreads();   // Q/K reads done -> V may overwrite Ks, stage may use Pb

    // ---- load V (over K) and mask+bias stage (into Pb) ----
    {
        const float* vbase = kvh + ((size_t)b * N2V) * (2 * DIM) + DIM + h * HD;
#pragma unroll
        for (int i = 0; i < 8; i++) {
            int li = tid + i * 256;
            int r  = li >> 3;
            int c4 = (li & 7) * 4;
            *(float4*)&Ks[r * SK + c4] =
                *(const float4*)(vbase + (size_t)r * (2 * DIM) + c4);
        }
        const float* maskb = mask  + ((size_t)(w * N1V + q0)) * N2V;
        const float* biasb = biasF + ((size_t)(h * N1V + q0)) * N2V;
#pragma unroll
        for (int i = 0; i < 16; i++) {
            int li = tid + i * 256;
            int r  = li >> 6;
            int c4 = (li & 63) * 4;
            float4 mv = *(const float4*)(maskb + (size_t)r * N2V + c4);
            float4 bv = *(const float4*)(biasb + (size_t)r * N2V + c4);
            float4 sv;
            sv.x = mv.x + bv.x; sv.y = mv.y + bv.y;
            sv.z = mv.z + bv.z; sv.w = mv.w + bv.w;
            *(float4*)&Pb[r * SP + c4] = sv;
        }
    }
    __syncthreads();

    // ---- add mask+bias; softmax via bfly over kg lane bits ----
#pragma unroll
    for (int i = 0; i < 4; i++)
#pragma unroll
        for (int j = 0; j < 16; j++)
            s[i][j] += Pb[(qi0 + i) * SP + 16 * j + kg];

    float linv[4];
#pragma unroll
    for (int i = 0; i < 4; i++) {
        float mx = s[i][0];
#pragma unroll
        for (int j = 1; j < 16; j++) mx = fmaxf(mx, s[i][j]);
        mx = fmaxf(mx, __shfl_xor_sync(0xFFFFFFFFu, mx, 1));
        mx = fmaxf(mx, __shfl_xor_sync(0xFFFFFFFFu, mx, 2));
        mx = fmaxf(mx, __shfl_xor_sync(0xFFFFFFFFu, mx, 4));
        mx = fmaxf(mx, __shfl_xor_sync(0xFFFFFFFFu, mx, 8));
        float ls = 0.f;
#pragma unroll
        for (int j = 0; j < 16; j++) {
            float e = __expf(s[i][j] - mx);
            s[i][j] = e;
            ls += e;
        }
        ls += __shfl_xor_sync(0xFFFFFFFFu, ls, 1);
        ls += __shfl_xor_sync(0xFFFFFFFFu, ls, 2);
        ls += __shfl_xor_sync(0xFFFFFFFFu, ls, 4);
        ls += __shfl_xor_sync(0xFFFFFFFFu, ls, 8);
        linv[i] = 1.0f / ls;
    }
    __syncthreads();   // stage reads done -> overwrite Pb with P

    // ---- store P (1/l folded) ----
#pragma unroll
    for (int i = 0; i < 4; i++)
#pragma unroll
        for (int j = 0; j < 16; j++)
            Pb[(qi0 + i) * SP + 16 * j + kg] = s[i][j] * linv[i];
    __syncthreads();

    // ---- PV: thread (q2, dg) -> queries {2q2,2q2+1} x dims {4dg..4dg+3} ----
    const int q2i = tid >> 3;      // 0..31
    const int dg  = tid & 7;       // 0..7
    ull o2[2][2];
    o2[0][0] = 0ull; o2[0][1] = 0ull; o2[1][0] = 0ull; o2[1][1] = 0ull;

#pragma unroll 4
    for (int k4 = 0; k4 < 64; k4++) {
        float4 pq0 = *(const float4*)&Pb[(2 * q2i)     * SP + k4 * 4];
        float4 pq1 = *(const float4*)&Pb[(2 * q2i + 1) * SP + k4 * 4];
        float p0a[4] = {pq0.x, pq0.y, pq0.z, pq0.w};
        float p1a[4] = {pq1.x, pq1.y, pq1.z, pq1.w};
#pragma unroll
        for (int kk = 0; kk < 4; kk++) {
            ulonglong2 vv = *(const ulonglong2*)&Ks[(k4 * 4 + kk) * SK + 4 * dg];
            ull pp0 = pack2(p0a[kk], p0a[kk]);
            ull pp1 = pack2(p1a[kk], p1a[kk]);
            ffma2(o2[0][0], pp0, vv.x); ffma2(o2[0][1], pp0, vv.y);
            ffma2(o2[1][0], pp1, vv.x); ffma2(o2[1][1], pp1, vv.y);
        }
    }

    // ---- write O: float4 per query ----
#pragma unroll
    for (int i = 0; i < 2; i++) {
        float4 v;
        unpack2(o2[i][0], v.x, v.y);
        unpack2(o2[i][1], v.z, v.w);
        *(float4*)(xout + ((size_t)(b * N1V + q0 + 2 * q2i + i)) * DIM
                   + h * HD + 4 * dg) = v;
    }
}

// ---------------- launch ----------------
extern "C" void kernel_launch(void* const* d_in, const int* in_sizes, int n_in,
                              void* d_out, int out_size)
{
    const float* q    = (const float*)d_in[0];
    const float* kv   = (const float*)d_in[1];
    const float* mask = (const float*)d_in[2];
    const float* Wq   = (const float*)d_in[3];
    const float* bq   = (const float*)d_in[4];
    const float* Wkv  = (const float*)d_in[5];
    const float* bkv  = (const float*)d_in[6];
    const float* btab = (const float*)d_in[7];
    const float* Wp   = (const float*)d_in[8];
    const float* bp   = (const float*)d_in[9];
    const int*   rel  = (const int*)d_in[10];
    float* out = (float*)d_out;

    static float* qh  = nullptr;
    static float* kvh = nullptr;
    static float* xb  = nullptr;
    static float* bF  = nullptr;
    if (!qh) {
        cudaGetSymbolAddress((void**)&qh,  d_qh);
        cudaGetSymbolAddress((void**)&kvh, d_kvh);
        cudaGetSymbolAddress((void**)&xb,  d_x);
        cudaGetSymbolAddress((void**)&bF,  d_biasF);
        cudaFuncSetAttribute(attn_kernel,
                             cudaFuncAttributeMaxDynamicSharedMemorySize,
                             ATTN_SMEM_BYTES);
    }

    const int M = MTOT;
    const float scale = 0.17677669529663687f;       // 1/sqrt(32)

    bias_pre<<<N1V * N2V / 256, 256>>>(btab, rel, bF);
    gemm_nt<<<dim3(DIM / 128, M / 128), 256>>>(q, Wq, bq, qh, M, DIM, DIM, scale);
    gemm_nt<<<dim3((2 * DIM) / 128, M / 128), 256>>>(kv, Wkv, bkv, kvh, M, 2 * DIM, DIM, 1.f);
    attn_kernel<<<dim3(4, HEADS, BTOT), 256, ATTN_SMEM_BYTES>>>(qh, kvh, mask, bF, xb);
    gemm_nt<<<dim3(DIM / 128, M / 128), 256>>>(xb, Wp, bp, out, M, DIM, DIM, 1.f);
}